// round 16
// baseline (speedup 1.0000x reference)
#include <cuda_runtime.h>
#include <cuda.h>
#include <math.h>
#include <stdint.h>

#define B_ 32
#define L_ 256
#define A_ 20
#define NTHR 864            // 20 consumers + pair + const + TMA producer + 4 LDG producers
#define TS 16               // tiles per stage
#define NSLOT 6
#define NSTAGE 16
#define STAGE_F 6400
#define STAGE_BYTES 25600

__device__ double g_res[L_][3];
__device__ unsigned int g_bcount = 0;

// smem layout (bytes):
//   0      .. 153600  ring: 6 slots x 25600
//   153600 .. 161792  xpk uint32[16][32][4]
//   161792 .. 161920  xi[32]
//   161920 .. 162000  wsrow[20]
//   162000 .. 162080  csts[20]
//   162080 .. 162160  sredr[20]
//   162160 .. 162256  mbarriers: slot r at +r*16 (full +0, empty +8)
//   162256 .. 162260  amLast
// epilogue reuse: lgbuf f32[32*21] @0, dred double[128] @byte 4096
#define SMEM_BYTES 162264
#define MB_OFF 162160

__device__ __forceinline__ uint32_t smem_u32(const void* p) {
    uint32_t a;
    asm("{ .reg .u64 t; cvta.to.shared.u64 t, %1; cvt.u32.u64 %0, t; }" : "=r"(a) : "l"(p));
    return a;
}
#define MB_INIT(addr, cnt) \
    asm volatile("mbarrier.init.shared.b64 [%0], %1;" :: "r"(addr), "r"(cnt) : "memory")
#define MB_EXPECT_TX(addr, bytes) \
    asm volatile("mbarrier.arrive.expect_tx.shared.b64 _, [%0], %1;" :: "r"(addr), "r"(bytes) : "memory")
#define MB_ARRIVE(addr) \
    asm volatile("mbarrier.arrive.shared.b64 _, [%0];" :: "r"(addr) : "memory")

__device__ __forceinline__ void mb_wait_acq(uint32_t mbar, uint32_t parity) {
    asm volatile(
        "{\n\t.reg .pred P;\n\t"
        "WL_%=:\n\t"
        "mbarrier.try_wait.parity.acquire.cta.shared::cta.b64 P, [%0], %1, 0x989680;\n\t"
        "@P bra.uni WD_%=;\n\t"
        "bra.uni WL_%=;\n\t"
        "WD_%=:\n\t}"
        :: "r"(mbar), "r"(parity) : "memory");
}
__device__ __forceinline__ void mb_wait_rlx(uint32_t mbar, uint32_t parity) {
    asm volatile(
        "{\n\t.reg .pred P;\n\t"
        "WL_%=:\n\t"
        "mbarrier.try_wait.parity.relaxed.cta.shared::cta.b64 P, [%0], %1, 0x989680;\n\t"
        "@P bra.uni WD_%=;\n\t"
        "bra.uni WL_%=;\n\t"
        "WD_%=:\n\t}"
        :: "r"(mbar), "r"(parity) : "memory");
}

__global__ __launch_bounds__(NTHR, 1) void mrf_kernel(const int* __restrict__ x,
                                                      const float* __restrict__ ws,
                                                      const float* __restrict__ wp,
                                                      float* __restrict__ out,
                                                      const __grid_constant__ CUtensorMap tmap) {
    extern __shared__ char smem_raw[];
    float*        bufs  = reinterpret_cast<float*>(smem_raw);
    uint32_t*     xpk   = reinterpret_cast<uint32_t*>(smem_raw + 153600);
    int*          xi    = reinterpret_cast<int*>(smem_raw + 161792);
    float*        wsrow = reinterpret_cast<float*>(smem_raw + 161920);
    float*        csts  = reinterpret_cast<float*>(smem_raw + 162000);
    float*        sredr = reinterpret_cast<float*>(smem_raw + 162080);
    int*          amLast= reinterpret_cast<int*>(smem_raw + 162256);
    const uint32_t mb0  = smem_u32(smem_raw + MB_OFF);
    const uint32_t bufa = smem_u32(smem_raw);

    const int i    = blockIdx.x;
    const int tid  = threadIdx.x;
    const int wid  = tid >> 5;
    const int lane = tid & 31;

    // full: even slots tx-based (count 1, TMA); odd slots count 4 (LDG warps).
    // empty: 22 arrivals (20 consumers + pair + const).
    if (tid == 0) {
        for (int r = 0; r < NSLOT; r++) {
            MB_INIT(mb0 + r * 16, (r & 1) ? 4u : 1u);
            MB_INIT(mb0 + r * 16 + 8, 22);
        }
    }

    // Pack x transpose, pre-scaled by 4.
    const int4* x4 = reinterpret_cast<const int4*>(x);
    for (int n = tid; n < 2048; n += NTHR) {
        int sidx = n >> 7, rem = n & 127;
        int b = rem >> 2, w = rem & 3;
        int4 q = x4[b * 64 + sidx * 4 + w];
        xpk[n] = (uint32_t)(q.x << 2) | ((uint32_t)(q.y << 2) << 8) |
                 ((uint32_t)(q.z << 2) << 16) | ((uint32_t)(q.w << 2) << 24);
    }
    if (tid < B_) xi[tid] = x[tid * L_ + i];
    if (tid >= 32 && tid < 52) wsrow[tid - 32] = ws[i * A_ + (tid - 32)];
    asm volatile("fence.proxy.async.shared::cta;" ::: "memory");
    __syncthreads();

    float acc = 0.f, pair = 0.f, c_acc = 0.f, reg1 = 0.f, reg2 = 0.f;

    if (wid < 20) {
        // ---- Consumers: warp = j, lane = b; gather p>i + reg pass ----
        const char* btj0 = smem_raw + wid * 80;
        const uint4* xpk4 = reinterpret_cast<const uint4*>(xpk);
        const float4* b4all = reinterpret_cast<const float4*>(smem_raw);
        const float2* b2all = reinterpret_cast<const float2*>(smem_raw);
        for (int sidx = 0; sidx < NSTAGE; sidx++) {
            const int slot = sidx % NSLOT;
            mb_wait_acq(mb0 + slot * 16, (sidx / NSLOT) & 1);

            {   // reg pass: 10 floats/lane
                float4 q1 = b4all[slot * 1600 + tid];
                float4 q2 = b4all[slot * 1600 + 640 + tid];
                float2 t2 = b2all[slot * 3200 + 2560 + tid];
                reg1 += fabsf(q1.x); reg2 = fmaf(q1.x, q1.x, reg2);
                reg1 += fabsf(q1.y); reg2 = fmaf(q1.y, q1.y, reg2);
                reg1 += fabsf(q1.z); reg2 = fmaf(q1.z, q1.z, reg2);
                reg1 += fabsf(q1.w); reg2 = fmaf(q1.w, q1.w, reg2);
                reg1 += fabsf(q2.x); reg2 = fmaf(q2.x, q2.x, reg2);
                reg1 += fabsf(q2.y); reg2 = fmaf(q2.y, q2.y, reg2);
                reg1 += fabsf(q2.z); reg2 = fmaf(q2.z, q2.z, reg2);
                reg1 += fabsf(q2.w); reg2 = fmaf(q2.w, q2.w, reg2);
                reg1 += fabsf(t2.x); reg2 = fmaf(t2.x, t2.x, reg2);
                reg1 += fabsf(t2.y); reg2 = fmaf(t2.y, t2.y, reg2);
            }

            const int pbase = sidx * TS;
            if (pbase + TS - 1 > i) {
                const char* btj = btj0 + slot * STAGE_BYTES;
                const uint4 u = xpk4[sidx * 32 + lane];
                const uint32_t wv[4] = {u.x, u.y, u.z, u.w};
                if (pbase > i) {
#pragma unroll
                    for (int k = 0; k < TS; k++) {
                        uint32_t e4 = __byte_perm(wv[k >> 2], 0, 0x4440 | (k & 3));
                        acc += *reinterpret_cast<const float*>(btj + k * 1600 + e4);
                    }
                } else {
#pragma unroll
                    for (int k = 0; k < TS; k++) {
                        uint32_t e4 = __byte_perm(wv[k >> 2], 0, 0x4440 | (k & 3));
                        if (pbase + k > i)
                            acc += *reinterpret_cast<const float*>(btj + k * 1600 + e4);
                    }
                }
            }
            if (lane == 0) MB_ARRIVE(mb0 + slot * 16 + 8);
        }
    } else if (wid == 20) {
        // ---- Pair warp: lane = b, all p ----
        const char* bt0 = smem_raw + xi[lane] * 80;
        const uint4* xpk4 = reinterpret_cast<const uint4*>(xpk);
        for (int sidx = 0; sidx < NSTAGE; sidx++) {
            const int slot = sidx % NSLOT;
            mb_wait_acq(mb0 + slot * 16, (sidx / NSLOT) & 1);
            const char* bt = bt0 + slot * STAGE_BYTES;
            const uint4 u = xpk4[sidx * 32 + lane];
            const uint32_t wv[4] = {u.x, u.y, u.z, u.w};
#pragma unroll
            for (int k = 0; k < TS; k++) {
                uint32_t e4 = __byte_perm(wv[k >> 2], 0, 0x4440 | (k & 3));
                pair += *reinterpret_cast<const float*>(bt + k * 1600 + e4);
            }
            if (lane == 0) MB_ARRIVE(mb0 + slot * 16 + 8);
        }
    } else if (wid == 21) {
        // ---- Const warp: lanes 0..19, j = lane ----
        const int j20 = lane * 20;
        for (int sidx = 0; sidx < NSTAGE; sidx++) {
            const int slot = sidx % NSLOT;
            mb_wait_acq(mb0 + slot * 16, (sidx / NSLOT) & 1);
            const int pbase = sidx * TS;
            if (lane < 20 && pbase <= i) {
                const float* bt = bufs + slot * STAGE_F;
                int tmax = i - pbase;
                int lim = tmax < TS ? tmax : TS;
                for (int t = 0; t < lim; t++) c_acc += bt[t * 400 + j20 + 19];
                if (tmax < TS) c_acc += bt[tmax * 400 + j20 + lane];
            }
            if (lane == 0) MB_ARRIVE(mb0 + slot * 16 + 8);
        }
    } else if (wid == 22) {
        // ---- TMA producer (lane 0): EVEN stages -> slots {0,2,4} ----
        if (lane == 0) {
            for (int s = 0; s < NSTAGE; s += 2) {
                const int slot = s % NSLOT;
                const int o = s / NSLOT;
                if (o >= 1) mb_wait_rlx(mb0 + slot * 16 + 8, (o - 1) & 1);
                MB_EXPECT_TX(mb0 + slot * 16, STAGE_BYTES);
                asm volatile(
                    "cp.async.bulk.tensor.3d.shared::cta.global.tile.mbarrier::complete_tx::bytes "
                    "[%0], [%1, {%2, %3, %4}], [%5];"
                    :: "r"(bufa + slot * STAGE_BYTES), "l"(&tmap),
                       "r"(0), "r"(s * 100), "r"(i),
                       "r"(mb0 + slot * 16) : "memory");
            }
        }
    } else {
        // ---- LDG producers (warps 23..26): ODD stages -> slots {1,3,5} ----
        const int wl = wid - 23;                    // 0..3
        const int base_lane = wl * 32 + lane;       // 0..127
        const float4* wp4 = reinterpret_cast<const float4*>(wp) + (size_t)i * 25600;
        float4* ring4 = reinterpret_cast<float4*>(smem_raw);
        for (int s = 1; s < NSTAGE; s += 2) {
            const int slot = s % NSLOT;
            const int o = s / NSLOT;
            if (o >= 1) mb_wait_rlx(mb0 + slot * 16 + 8, (o - 1) & 1);
            const float4* src = wp4 + s * 1600;
            float4 v[13];
#pragma unroll
            for (int c = 0; c < 12; c++) v[c] = src[base_lane + c * 128];
            if (base_lane < 64) v[12] = src[base_lane + 1536];
#pragma unroll
            for (int c = 0; c < 12; c++) ring4[slot * 1600 + base_lane + c * 128] = v[c];
            if (base_lane < 64) ring4[slot * 1600 + base_lane + 1536] = v[12];
            __syncwarp();
            if (lane == 0) MB_ARRIVE(mb0 + slot * 16);   // full: count 4
        }
    }

    // ---------------- Epilogue ----------------
    if (wid == 21 && lane < 20) csts[lane] = c_acc;
    if (wid < 20) {
        float rv = reg1 + reg2;
#pragma unroll
        for (int o = 16; o > 0; o >>= 1) rv += __shfl_down_sync(0xffffffffu, rv, o);
        if (lane == 0) sredr[wid] = rv;
    }
    if (wid == 20) {
        double pv = (double)pair;
#pragma unroll
        for (int o = 16; o > 0; o >>= 1) pv += __shfl_down_sync(0xffffffffu, pv, o);
        if (lane == 0) g_res[i][1] = pv;
    }
    __syncthreads();

    if (wid < 20) bufs[lane * 21 + wid] = acc + csts[wid] + wsrow[wid];  // lgbuf[b*21+j]
    __syncthreads();

    if (tid < 32) {       // lse per b, minus single
        const float* row = &bufs[tid * 21];
        float m = row[0];
#pragma unroll
        for (int j = 1; j < A_; j++) m = fmaxf(m, row[j]);
        float se = 0.f;
#pragma unroll
        for (int j = 0; j < A_; j++) se += __expf(row[j] - m);
        float lse = m + __logf(se);
        double val = (double)lse - (double)wsrow[xi[tid]];
#pragma unroll
        for (int o = 16; o > 0; o >>= 1) val += __shfl_down_sync(0xffffffffu, val, o);
        if (tid == 0) g_res[i][0] = val;
    } else if (tid < 64) {
        double rv = (lane < 20) ? (double)sredr[lane] : 0.0;
#pragma unroll
        for (int o = 16; o > 0; o >>= 1) rv += __shfl_down_sync(0xffffffffu, rv, o);
        if (lane == 0) g_res[i][2] = rv;
    }
    __syncthreads();

    // ---- Fused deterministic final reduction (last CTA) ----
    if (tid == 0) {
        __threadfence();
        *amLast = (atomicAdd(&g_bcount, 1u) == (unsigned)(gridDim.x - 1)) ? 1 : 0;
    }
    __syncthreads();
    if (!*amLast) return;
    __threadfence();

    double LS = 0.0, PA = 0.0, RP = 0.0, RS = 0.0;
    if (tid < L_) { LS = g_res[tid][0]; PA = g_res[tid][1]; RP = g_res[tid][2]; }
    for (int n = tid; n < L_ * A_; n += NTHR) {
        float w = ws[n];
        RS += (double)fabsf(w) + (double)w * (double)w;
    }
    double* dred = reinterpret_cast<double*>(smem_raw + 4096);
#pragma unroll
    for (int o = 16; o > 0; o >>= 1) {
        LS += __shfl_down_sync(0xffffffffu, LS, o);
        PA += __shfl_down_sync(0xffffffffu, PA, o);
        RP += __shfl_down_sync(0xffffffffu, RP, o);
        RS += __shfl_down_sync(0xffffffffu, RS, o);
    }
    if (lane == 0) {
        dred[wid] = LS; dred[32 + wid] = PA; dred[64 + wid] = RP; dred[96 + wid] = RS;
    }
    __syncthreads();
    if (tid == 0) {
        double ls = 0, pa = 0, rp = 0, rs = 0;
        for (int w = 0; w < 27; w++) {
            ls += dred[w]; pa += dred[32 + w]; rp += dred[64 + w]; rs += dred[96 + w];
        }
        // LAMBDA_SINGLE = 1.0, LAMBDA_PAIR = 0.2*(L-1) = 51.0
        out[0] = (float)((ls - pa) / (double)B_ + 1.0 * rs + 51.0 * rp);
        g_bcount = 0;
    }
}

typedef CUresult (*EncodeFn)(CUtensorMap*, CUtensorMapDataType, cuuint32_t, void*,
                             const cuuint64_t*, const cuuint64_t*,
                             const cuuint32_t*, const cuuint32_t*,
                             CUtensorMapInterleave, CUtensorMapSwizzle,
                             CUtensorMapL2promotion, CUtensorMapFloatOOBfill);

extern "C" void kernel_launch(void* const* d_in, const int* in_sizes, int n_in,
                              void* d_out, int out_size) {
    (void)in_sizes; (void)n_in; (void)out_size;
    const int*   x  = (const int*)d_in[0];
    const float* ws = (const float*)d_in[1];
    const float* wp = (const float*)d_in[2];
    float* out = (float*)d_out;

    static CUtensorMap tmap;
    void* fn = nullptr;
    cudaDriverEntryPointQueryResult qst;
    cudaGetDriverEntryPointByVersion("cuTensorMapEncodeTiled", &fn, 12000,
                                     cudaEnableDefault, &qst);
    EncodeFn enc = (EncodeFn)fn;
    cuuint64_t dims[3]    = {256, 1600, 256};
    cuuint64_t strides[2] = {256, 409600};
    cuuint32_t box[3]     = {256, 100, 1};
    cuuint32_t es[3]      = {1, 1, 1};
    enc(&tmap, CU_TENSOR_MAP_DATA_TYPE_UINT8, 3, (void*)wp,
        dims, strides, box, es,
        CU_TENSOR_MAP_INTERLEAVE_NONE, CU_TENSOR_MAP_SWIZZLE_NONE,
        CU_TENSOR_MAP_L2_PROMOTION_L2_128B, CU_TENSOR_MAP_FLOAT_OOB_FILL_NONE);

    cudaFuncSetAttribute(mrf_kernel, cudaFuncAttributeMaxDynamicSharedMemorySize, SMEM_BYTES);
    mrf_kernel<<<L_, NTHR, SMEM_BYTES>>>(x, ws, wp, out, tmap);
}

// round 17
// speedup vs baseline: 1.3596x; 1.3596x over previous
#include <cuda_runtime.h>
#include <cuda.h>
#include <math.h>
#include <stdint.h>

#define B_ 32
#define L_ 256
#define A_ 20
#define NTHR 736            // 20 consumer warps + producer + pair + const
#define TS 16               // tiles per stage
#define RING 3
#define NSTAGE 16           // 256 tiles / 16
#define STAGE_F 6400
#define STAGE_BYTES 25600

__device__ double g_res[L_][3];          // per-i {lse_sum, pair_sum, reg_sum}
__device__ unsigned int g_bcount = 0;    // reset by last block each launch

// smem layout (bytes):
//   0     .. 76800  ring data (3 x 25600), row-major tiles
//   76800 .. 84992  xpk uint32[16 sidx][32 b][4 g]: bytes 4*x[b][p]
//   84992 .. 85120  xi[32]
//   85120 .. 85200  wsrow[20]
//   85200 .. 85280  csts[20]
//   85280 .. 85360  sredr[20]
//   85360 .. 85408  mbarriers per r (stride 16): full +0, empty +8
//   85408 .. 85412  amLast
// epilogue reuse: lgbuf f32[32*21] @0, dred double[4*32] @byte 4096
#define SMEM_BYTES 85424
#define MB_OFF 85360

__device__ __forceinline__ uint32_t smem_u32(const void* p) {
    uint32_t a;
    asm("{ .reg .u64 t; cvta.to.shared.u64 t, %1; cvt.u32.u64 %0, t; }" : "=r"(a) : "l"(p));
    return a;
}
#define MB_INIT(addr, cnt) \
    asm volatile("mbarrier.init.shared.b64 [%0], %1;" :: "r"(addr), "r"(cnt) : "memory")
#define MB_EXPECT_TX(addr, bytes) \
    asm volatile("mbarrier.arrive.expect_tx.shared.b64 _, [%0], %1;" :: "r"(addr), "r"(bytes) : "memory")
#define MB_ARRIVE(addr) \
    asm volatile("mbarrier.arrive.shared.b64 _, [%0];" :: "r"(addr) : "memory")

__device__ __forceinline__ void mb_wait_acq(uint32_t mbar, uint32_t parity) {
    asm volatile(
        "{\n\t.reg .pred P;\n\t"
        "WL_%=:\n\t"
        "mbarrier.try_wait.parity.acquire.cta.shared::cta.b64 P, [%0], %1, 0x989680;\n\t"
        "@P bra.uni WD_%=;\n\t"
        "bra.uni WL_%=;\n\t"
        "WD_%=:\n\t}"
        :: "r"(mbar), "r"(parity) : "memory");
}
__device__ __forceinline__ void mb_wait_rlx(uint32_t mbar, uint32_t parity) {
    asm volatile(
        "{\n\t.reg .pred P;\n\t"
        "WL_%=:\n\t"
        "mbarrier.try_wait.parity.relaxed.cta.shared::cta.b64 P, [%0], %1, 0x989680;\n\t"
        "@P bra.uni WD_%=;\n\t"
        "bra.uni WL_%=;\n\t"
        "WD_%=:\n\t}"
        :: "r"(mbar), "r"(parity) : "memory");
}

__global__ __launch_bounds__(NTHR, 2) void mrf_kernel(const int* __restrict__ x,
                                                      const float* __restrict__ ws,
                                                      float* __restrict__ out,
                                                      const __grid_constant__ CUtensorMap tmap) {
    extern __shared__ char smem_raw[];
    float*        bufs  = reinterpret_cast<float*>(smem_raw);
    uint32_t*     xpk   = reinterpret_cast<uint32_t*>(smem_raw + 76800);
    int*          xi    = reinterpret_cast<int*>(smem_raw + 84992);
    float*        wsrow = reinterpret_cast<float*>(smem_raw + 85120);
    float*        csts  = reinterpret_cast<float*>(smem_raw + 85200);
    float*        sredr = reinterpret_cast<float*>(smem_raw + 85280);
    int*          amLast= reinterpret_cast<int*>(smem_raw + 85408);
    const uint32_t mb0  = smem_u32(smem_raw + MB_OFF);
    const uint32_t bufa = smem_u32(smem_raw);

    const int i    = blockIdx.x;
    const int tid  = threadIdx.x;
    const int wid  = tid >> 5;
    const int lane = tid & 31;

    // full: tx-based (count 1). empty: 22 arrivals (20 consumers + pair + const).
    if (tid == 0) {
        for (int r = 0; r < RING; r++) {
            MB_INIT(mb0 + r * 16, 1);
            MB_INIT(mb0 + r * 16 + 8, 22);
        }
    }

    // Pack x transpose, pre-scaled by 4: xpk[sidx*128 + lane*4 + w] holds bytes
    // 4*x[b=lane][p = sidx*16 + 4w .. +3]
    const int4* x4 = reinterpret_cast<const int4*>(x);
    for (int n = tid; n < 2048; n += NTHR) {
        int sidx = n >> 7, rem = n & 127;
        int b = rem >> 2, w = rem & 3;
        int4 q = x4[b * 64 + sidx * 4 + w];
        xpk[n] = (uint32_t)(q.x << 2) | ((uint32_t)(q.y << 2) << 8) |
                 ((uint32_t)(q.z << 2) << 16) | ((uint32_t)(q.w << 2) << 24);
    }
    if (tid < B_) xi[tid] = x[tid * L_ + i];
    if (tid >= 32 && tid < 52) wsrow[tid - 32] = ws[i * A_ + (tid - 32)];
    asm volatile("fence.proxy.async.shared::cta;" ::: "memory");
    __syncthreads();

    float acc = 0.f, pair = 0.f, c_acc = 0.f, reg1 = 0.f, reg2 = 0.f;

    if (wid < 20) {
        // ---- Consumers: warp = j, lane = b; gather p>i + reg pass ----
        const char* btj0 = smem_raw + wid * 80;   // + r*STAGE_BYTES later
        const uint4* xpk4 = reinterpret_cast<const uint4*>(xpk);
        const float4* b4all = reinterpret_cast<const float4*>(smem_raw);
        const float2* b2all = reinterpret_cast<const float2*>(smem_raw);
        int r = 0, ph = 0;
        for (int sidx = 0; sidx < NSTAGE; sidx++) {
            mb_wait_acq(mb0 + r * 16, ph);

            // reg pass: 10 floats/lane (2 x LDS.128 + 1 x LDS.64)
            {
                float4 q1 = b4all[r * 1600 + tid];
                float4 q2 = b4all[r * 1600 + 640 + tid];
                float2 t2 = b2all[r * 3200 + 2560 + tid];
                reg1 += fabsf(q1.x); reg2 = fmaf(q1.x, q1.x, reg2);
                reg1 += fabsf(q1.y); reg2 = fmaf(q1.y, q1.y, reg2);
                reg1 += fabsf(q1.z); reg2 = fmaf(q1.z, q1.z, reg2);
                reg1 += fabsf(q1.w); reg2 = fmaf(q1.w, q1.w, reg2);
                reg1 += fabsf(q2.x); reg2 = fmaf(q2.x, q2.x, reg2);
                reg1 += fabsf(q2.y); reg2 = fmaf(q2.y, q2.y, reg2);
                reg1 += fabsf(q2.z); reg2 = fmaf(q2.z, q2.z, reg2);
                reg1 += fabsf(q2.w); reg2 = fmaf(q2.w, q2.w, reg2);
                reg1 += fabsf(t2.x); reg2 = fmaf(t2.x, t2.x, reg2);
                reg1 += fabsf(t2.y); reg2 = fmaf(t2.y, t2.y, reg2);
            }

            const int pbase = sidx * TS;
            if (pbase + TS - 1 > i) {
                const char* btj = btj0 + r * STAGE_BYTES;
                const uint4 u = xpk4[sidx * 32 + lane];
                const uint32_t wv[4] = {u.x, u.y, u.z, u.w};
                if (pbase > i) {          // ABOVE: all 16 tiles
#pragma unroll
                    for (int k = 0; k < TS; k++) {
                        uint32_t e4 = __byte_perm(wv[k >> 2], 0, 0x4440 | (k & 3));
                        acc += *reinterpret_cast<const float*>(btj + k * 1600 + e4);
                    }
                } else {                  // MIXED
#pragma unroll
                    for (int k = 0; k < TS; k++) {
                        uint32_t e4 = __byte_perm(wv[k >> 2], 0, 0x4440 | (k & 3));
                        if (pbase + k > i)
                            acc += *reinterpret_cast<const float*>(btj + k * 1600 + e4);
                    }
                }
            }
            if (lane == 0) MB_ARRIVE(mb0 + r * 16 + 8);
            if (++r == RING) { r = 0; ph ^= 1; }
        }
    } else if (wid == 20) {
        // ---- Producer (lane 0): tensor TMA with WIDE rows (1600B x 16) ----
        if (lane == 0) {
            int r = 0, wr = 0, wph = 0;
            for (int sidx = 0; sidx < NSTAGE; sidx++) {
                if (sidx >= RING) {
                    mb_wait_rlx(mb0 + wr * 16 + 8, wph);
                    if (++wr == RING) { wr = 0; wph ^= 1; }
                }
                MB_EXPECT_TX(mb0 + r * 16, STAGE_BYTES);
                asm volatile(
                    "cp.async.bulk.tensor.2d.shared::cta.global.tile.mbarrier::complete_tx::bytes "
                    "[%0], [%1, {%2, %3}], [%4];"
                    :: "r"(bufa + r * STAGE_BYTES), "l"(&tmap),
                       "r"(0), "r"(i * 256 + sidx * 16),
                       "r"(mb0 + r * 16) : "memory");
                if (++r == RING) r = 0;
            }
        }
    } else if (wid == 21) {
        // ---- Pair warp: lane = b, all p ----
        const char* bt0 = smem_raw + xi[lane] * 80;
        const uint4* xpk4 = reinterpret_cast<const uint4*>(xpk);
        int r = 0, ph = 0;
        for (int sidx = 0; sidx < NSTAGE; sidx++) {
            mb_wait_acq(mb0 + r * 16, ph);
            const char* bt = bt0 + r * STAGE_BYTES;
            const uint4 u = xpk4[sidx * 32 + lane];
            const uint32_t wv[4] = {u.x, u.y, u.z, u.w};
#pragma unroll
            for (int k = 0; k < TS; k++) {
                uint32_t e4 = __byte_perm(wv[k >> 2], 0, 0x4440 | (k & 3));
                pair += *reinterpret_cast<const float*>(bt + k * 1600 + e4);
            }
            if (lane == 0) MB_ARRIVE(mb0 + r * 16 + 8);
            if (++r == RING) { r = 0; ph ^= 1; }
        }
    } else {
        // ---- Const warp: lanes 0..19, j = lane ----
        const int j20 = lane * 20;
        int r = 0, ph = 0;
        for (int sidx = 0; sidx < NSTAGE; sidx++) {
            mb_wait_acq(mb0 + r * 16, ph);
            const int pbase = sidx * TS;
            if (lane < 20 && pbase <= i) {
                const float* bt = bufs + r * STAGE_F;
                int tmax = i - pbase;              // t < tmax  <=>  p < i
                int lim = tmax < TS ? tmax : TS;
                for (int t = 0; t < lim; t++) c_acc += bt[t * 400 + j20 + 19];
                if (tmax < TS) c_acc += bt[tmax * 400 + j20 + lane];   // diag p==i
            }
            if (lane == 0) MB_ARRIVE(mb0 + r * 16 + 8);
            if (++r == RING) { r = 0; ph ^= 1; }
        }
    }

    // ---------------- Epilogue ----------------
    if (wid == 22 && lane < 20) csts[lane] = c_acc;
    if (wid < 20) {
        float rv = reg1 + reg2;
#pragma unroll
        for (int o = 16; o > 0; o >>= 1) rv += __shfl_down_sync(0xffffffffu, rv, o);
        if (lane == 0) sredr[wid] = rv;
    }
    if (wid == 21) {
        double pv = (double)pair;
#pragma unroll
        for (int o = 16; o > 0; o >>= 1) pv += __shfl_down_sync(0xffffffffu, pv, o);
        if (lane == 0) g_res[i][1] = pv;
    }
    __syncthreads();

    if (wid < 20) bufs[lane * 21 + wid] = acc + csts[wid] + wsrow[wid];  // lgbuf[b*21+j]
    __syncthreads();

    if (tid < 32) {       // lse per b, minus single
        const float* row = &bufs[tid * 21];
        float m = row[0];
#pragma unroll
        for (int j = 1; j < A_; j++) m = fmaxf(m, row[j]);
        float se = 0.f;
#pragma unroll
        for (int j = 0; j < A_; j++) se += __expf(row[j] - m);
        float lse = m + __logf(se);
        double val = (double)lse - (double)wsrow[xi[tid]];
#pragma unroll
        for (int o = 16; o > 0; o >>= 1) val += __shfl_down_sync(0xffffffffu, val, o);
        if (tid == 0) g_res[i][0] = val;
    } else if (tid < 64) {   // reg sum over 20 warps
        double rv = (lane < 20) ? (double)sredr[lane] : 0.0;
#pragma unroll
        for (int o = 16; o > 0; o >>= 1) rv += __shfl_down_sync(0xffffffffu, rv, o);
        if (lane == 0) g_res[i][2] = rv;
    }
    __syncthreads();

    // ---------------- Fused deterministic final reduction (last CTA) ----------------
    if (tid == 0) {
        __threadfence();
        *amLast = (atomicAdd(&g_bcount, 1u) == (unsigned)(gridDim.x - 1)) ? 1 : 0;
    }
    __syncthreads();
    if (!*amLast) return;
    __threadfence();

    double LS = 0.0, PA = 0.0, RP = 0.0, RS = 0.0;
    if (tid < L_) { LS = g_res[tid][0]; PA = g_res[tid][1]; RP = g_res[tid][2]; }
    for (int n = tid; n < L_ * A_; n += NTHR) {
        float w = ws[n];
        RS += (double)fabsf(w) + (double)w * (double)w;
    }
    double* dred = reinterpret_cast<double*>(smem_raw + 4096);
#pragma unroll
    for (int o = 16; o > 0; o >>= 1) {
        LS += __shfl_down_sync(0xffffffffu, LS, o);
        PA += __shfl_down_sync(0xffffffffu, PA, o);
        RP += __shfl_down_sync(0xffffffffu, RP, o);
        RS += __shfl_down_sync(0xffffffffu, RS, o);
    }
    if (lane == 0) {
        dred[wid] = LS; dred[32 + wid] = PA; dred[64 + wid] = RP; dred[96 + wid] = RS;
    }
    __syncthreads();
    if (tid == 0) {
        double ls = 0, pa = 0, rp = 0, rs = 0;
        for (int w = 0; w < 23; w++) {
            ls += dred[w]; pa += dred[32 + w]; rp += dred[64 + w]; rs += dred[96 + w];
        }
        // LAMBDA_SINGLE = 1.0, LAMBDA_PAIR = 0.2*(L-1) = 51.0
        out[0] = (float)((ls - pa) / (double)B_ + 1.0 * rs + 51.0 * rp);
        g_bcount = 0;   // self-reset for graph replay
    }
}

typedef CUresult (*EncodeFn)(CUtensorMap*, CUtensorMapDataType, cuuint32_t, void*,
                             const cuuint64_t*, const cuuint64_t*,
                             const cuuint32_t*, const cuuint32_t*,
                             CUtensorMapInterleave, CUtensorMapSwizzle,
                             CUtensorMapL2promotion, CUtensorMapFloatOOBfill);

extern "C" void kernel_launch(void* const* d_in, const int* in_sizes, int n_in,
                              void* d_out, int out_size) {
    (void)in_sizes; (void)n_in; (void)out_size;
    const int*   x  = (const int*)d_in[0];
    const float* ws = (const float*)d_in[1];
    const float* wp = (const float*)d_in[2];
    float* out = (float*)d_out;

    // Tensormap with WIDE rows: one row = one 20x20 tile = 1600 B (200 x u64).
    // dims: [200 u64, 65536 tiles]; box [200, 16] = 25.6 KB stage, 16 rows.
    static CUtensorMap tmap;
    void* fn = nullptr;
    cudaDriverEntryPointQueryResult qst;
    cudaGetDriverEntryPointByVersion("cuTensorMapEncodeTiled", &fn, 12000,
                                     cudaEnableDefault, &qst);
    EncodeFn enc = (EncodeFn)fn;
    cuuint64_t dims[2]    = {200, 65536};
    cuuint64_t strides[1] = {1600};                  // bytes between rows
    cuuint32_t box[2]     = {200, 16};               // 1600B x 16 rows = 25.6 KB
    cuuint32_t es[2]      = {1, 1};
    enc(&tmap, CU_TENSOR_MAP_DATA_TYPE_UINT64, 2, (void*)wp,
        dims, strides, box, es,
        CU_TENSOR_MAP_INTERLEAVE_NONE, CU_TENSOR_MAP_SWIZZLE_NONE,
        CU_TENSOR_MAP_L2_PROMOTION_L2_128B, CU_TENSOR_MAP_FLOAT_OOB_FILL_NONE);

    cudaFuncSetAttribute(mrf_kernel, cudaFuncAttributeMaxDynamicSharedMemorySize, SMEM_BYTES);
    mrf_kernel<<<L_, NTHR, SMEM_BYTES>>>(x, ws, out, tmap);
}